// round 6
// baseline (speedup 1.0000x reference)
#include <cuda_runtime.h>

// Gumbel-Sinkhorn, multiplicative form, persistent dual-resident design.
//
//   E = exp((gamma + noise) * 5)
//   repeat niters: r_i = 1/sum_j E_ij c_j ;  c_j = 1/sum_i E_ij r_i
//   out_ij = E_ij * r_i * c_j
//
// Persistent kernel: grid = #SMs, one 512-thread CTA per SM, each CTA loops
// over matrices bid, bid+grid, ... with cp.async double-buffered noise
// prefetch into smem (load of matrix m+grid overlaps iterations of m).
//
// Thread t = (r4 = t>>2, q = t&3) holds in registers:
//   rowE: E[r4][32q .. 32q+31]      (row pass operand)
//   colE: E[32q .. 32q+31][r4]      (col pass operand, i.e. E^T)
// Both Sinkhorn passes are pure packed f32x2 FFMA on registers; per-iteration
// shared-memory traffic is only broadcast reads of r/c from 4 bank-staggered
// replicas (stride 136 floats -> replica q's reads hit banks 8q+4m: conflict-
// free, 1 cycle per LDS.128) plus one scalar store per thread per pass.

#define NN 128
#define STRIDE 132        // padded E row stride (floats); col reads conflict-light
#define REP 136           // replica stride for r/c vectors (floats)
#define NT 512

typedef unsigned long long ull;

__device__ __forceinline__ ull pack2(float lo, float hi) {
    ull r; asm("mov.b64 %0, {%1, %2};" : "=l"(r) : "f"(lo), "f"(hi)); return r;
}
__device__ __forceinline__ void unpack2(ull v, float& lo, float& hi) {
    asm("mov.b64 {%0, %1}, %2;" : "=f"(lo), "=f"(hi) : "l"(v));
}
__device__ __forceinline__ void fma2(ull& d, ull a, ull b) {
    asm("fma.rn.f32x2 %0, %1, %2, %0;" : "+l"(d) : "l"(a), "l"(b));
}
__device__ __forceinline__ ull add2(ull a, ull b) {
    ull r; asm("add.rn.f32x2 %0, %1, %2;" : "=l"(r) : "l"(a), "l"(b)); return r;
}

__device__ __forceinline__ void prefetch_noise(const float* noise, long long m,
                                               float* dst, int tid) {
    const float4* src = reinterpret_cast<const float4*>(noise + m * (NN * NN));
    #pragma unroll
    for (int k = 0; k < 8; ++k) {
        int v  = k * NT + tid;          // float4 index 0..4095
        int i  = v >> 5;
        int jf = (v & 31) * 4;
        unsigned int daddr = (unsigned int)__cvta_generic_to_shared(&dst[i * STRIDE + jf]);
        asm volatile("cp.async.cg.shared.global [%0], [%1], 16;\n"
                     :: "r"(daddr), "l"(src + v) : "memory");
    }
    asm volatile("cp.async.commit_group;" ::: "memory");
}

__global__ __launch_bounds__(NT, 1) void sinkhorn_persistent(
    const float* __restrict__ gamma,
    const float* __restrict__ noise,
    const int*   __restrict__ niters_p,
    float*       __restrict__ out,
    int B)
{
    extern __shared__ float smem[];
    float* Es0  = smem;                       // NN*STRIDE
    float* Es1  = Es0 + NN * STRIDE;          // NN*STRIDE
    float* g5   = Es1 + NN * STRIDE;          // NN*NN  (gamma * 5, packed rows)
    float* rrep = g5 + NN * NN;               // 4*REP
    float* crep = rrep + 4 * REP;             // 4*REP

    const int tid = threadIdx.x;
    const int q   = tid & 3;
    const int r4  = tid >> 2;
    const int niters = *niters_p;
    const int grid   = gridDim.x;

    // ---- g5 = gamma * 5 (once) ----
    {
        const float4* g4 = reinterpret_cast<const float4*>(gamma);
        float4* g54 = reinterpret_cast<float4*>(g5);
        #pragma unroll
        for (int k = 0; k < 8; ++k) {
            int v = k * NT + tid;
            float4 g = g4[v];
            g.x *= 5.f; g.y *= 5.f; g.z *= 5.f; g.w *= 5.f;
            g54[v] = g;
        }
    }

    if (blockIdx.x >= B) return;              // uniform per CTA

    // ---- first prefetch ----
    prefetch_noise(noise, blockIdx.x, Es0, tid);

    int buf = 0;
    for (long long m = blockIdx.x; m < B; m += grid, buf ^= 1) {
        float* Es = buf ? Es1 : Es0;
        float* En = buf ? Es0 : Es1;

        asm volatile("cp.async.wait_group 0;" ::: "memory");
        __syncthreads();                      // noise(m) visible to all

        // ---- transform in place: Es = exp(g5 + 5*noise) ----
        #pragma unroll
        for (int k = 0; k < 8; ++k) {
            int v  = k * NT + tid;
            int i  = v >> 5;
            int jf = (v & 31) * 4;
            float4* p = reinterpret_cast<float4*>(&Es[i * STRIDE + jf]);
            float4 n = *p;
            float4 g = reinterpret_cast<const float4*>(g5)[v];
            float4 e;
            e.x = __expf(fmaf(n.x, 5.f, g.x));
            e.y = __expf(fmaf(n.y, 5.f, g.y));
            e.z = __expf(fmaf(n.z, 5.f, g.z));
            e.w = __expf(fmaf(n.w, 5.f, g.w));
            *p = e;
        }
        // init c replicas to 1
        if (tid < 4 * REP) crep[tid] = 1.0f;
        if (tid < 4 * REP - NT) crep[NT + tid] = 1.0f;
        __syncthreads();                      // Es + crep ready

        // ---- fill register row/col caches ----
        ull rE[16], cE[16];
        #pragma unroll
        for (int mm = 0; mm < 8; ++mm) {
            float4 e = *reinterpret_cast<const float4*>(&Es[r4 * STRIDE + 32 * q + 4 * mm]);
            rE[2 * mm + 0] = pack2(e.x, e.y);
            rE[2 * mm + 1] = pack2(e.z, e.w);
        }
        #pragma unroll
        for (int p = 0; p < 16; ++p) {
            float lo = Es[(32 * q + 2 * p + 0) * STRIDE + r4];
            float hi = Es[(32 * q + 2 * p + 1) * STRIDE + r4];
            cE[p] = pack2(lo, hi);
        }

        // ---- prefetch next matrix into the other buffer (overlaps iters) ----
        if (m + grid < B) prefetch_noise(noise, m + grid, En, tid);

        // ---- Sinkhorn iterations ----
        const float* crd = &crep[168 * q];    // 136*q + 32*q
        const float* rrd = &rrep[168 * q];
        float* rwr = &rrep[REP * q + r4];
        float* cwr = &crep[REP * q + r4];

        for (int it = 0; it < niters; ++it) {
            // Row pass: S_{r4} partial over j in [32q, 32q+32)
            ull a0 = pack2(0.f, 0.f), a1 = a0, a2 = a0, a3 = a0;
            #pragma unroll
            for (int mm = 0; mm < 4; ++mm) {
                float4 c0 = *reinterpret_cast<const float4*>(&crd[8 * mm]);
                float4 c1 = *reinterpret_cast<const float4*>(&crd[8 * mm + 4]);
                fma2(a0, rE[4 * mm + 0], pack2(c0.x, c0.y));
                fma2(a1, rE[4 * mm + 1], pack2(c0.z, c0.w));
                fma2(a2, rE[4 * mm + 2], pack2(c1.x, c1.y));
                fma2(a3, rE[4 * mm + 3], pack2(c1.z, c1.w));
            }
            ull as = add2(add2(a0, a1), add2(a2, a3));
            float slo, shi; unpack2(as, slo, shi);
            float S = slo + shi;
            S += __shfl_xor_sync(0xffffffffu, S, 1);
            S += __shfl_xor_sync(0xffffffffu, S, 2);
            *rwr = __fdividef(1.0f, S);
            __syncthreads();

            // Col pass: T_{r4} partial over i in [32q, 32q+32)
            ull b0 = pack2(0.f, 0.f), b1 = b0, b2 = b0, b3 = b0;
            #pragma unroll
            for (int mm = 0; mm < 4; ++mm) {
                float4 r0 = *reinterpret_cast<const float4*>(&rrd[8 * mm]);
                float4 r1 = *reinterpret_cast<const float4*>(&rrd[8 * mm + 4]);
                fma2(b0, cE[4 * mm + 0], pack2(r0.x, r0.y));
                fma2(b1, cE[4 * mm + 1], pack2(r0.z, r0.w));
                fma2(b2, cE[4 * mm + 2], pack2(r1.x, r1.y));
                fma2(b3, cE[4 * mm + 3], pack2(r1.z, r1.w));
            }
            ull bs = add2(add2(b0, b1), add2(b2, b3));
            float tlo, thi; unpack2(bs, tlo, thi);
            float Tv = tlo + thi;
            Tv += __shfl_xor_sync(0xffffffffu, Tv, 1);
            Tv += __shfl_xor_sync(0xffffffffu, Tv, 2);
            *cwr = __fdividef(1.0f, Tv);
            __syncthreads();
        }

        // ---- epilogue: out = E * r * c (replica 0 of r/c) ----
        float4* o4 = reinterpret_cast<float4*>(out + m * (NN * NN));
        #pragma unroll
        for (int k = 0; k < 8; ++k) {
            int v  = k * NT + tid;
            int i  = v >> 5;
            int jf = (v & 31) * 4;
            float ri = rrep[i];
            float4 c = *reinterpret_cast<const float4*>(&crep[jf]);
            float4 e = *reinterpret_cast<const float4*>(&Es[i * STRIDE + jf]);
            float4 o;
            o.x = e.x * ri * c.x;
            o.y = e.y * ri * c.y;
            o.z = e.z * ri * c.z;
            o.w = e.w * ri * c.w;
            o4[v] = o;
        }
        __syncthreads();  // Es must be fully read before it becomes a prefetch dst
    }
}

extern "C" void kernel_launch(void* const* d_in, const int* in_sizes, int n_in,
                              void* d_out, int out_size)
{
    // Identify inputs by element count:
    //   gamma: 128*128, noise: B*128*128 (largest), niters: 1
    int gi = -1, ni = -1, si = -1;
    long long best = -1;
    for (int k = 0; k < n_in; ++k) {
        if (in_sizes[k] == 1) { si = k; }
        else if (in_sizes[k] == NN * NN && gi < 0) { gi = k; }
        if ((long long)in_sizes[k] > best) { best = in_sizes[k]; ni = k; }
    }
    if (ni == gi) {
        for (int k = 0; k < n_in; ++k)
            if (k != gi && in_sizes[k] == NN * NN) { ni = k; break; }
    }

    const float* gamma = (const float*)d_in[gi];
    const float* noise = (const float*)d_in[ni];
    const int*   nit   = (const int*)d_in[si];
    float* out = (float*)d_out;

    int B = in_sizes[ni] / (NN * NN);

    const int smem_bytes = (2 * NN * STRIDE + NN * NN + 8 * REP) * (int)sizeof(float);

    static int smcount = 0;
    if (!smcount) {
        int dev = 0;
        cudaGetDevice(&dev);
        cudaDeviceGetAttribute(&smcount, cudaDevAttrMultiProcessorCount, dev);
        if (smcount <= 0) smcount = 148;
        cudaFuncSetAttribute(sinkhorn_persistent,
                             cudaFuncAttributeMaxDynamicSharedMemorySize,
                             smem_bytes);
    }

    int grid = smcount < B ? smcount : B;
    sinkhorn_persistent<<<grid, NT, smem_bytes>>>(gamma, noise, nit, out, B);
}

// round 7
// speedup vs baseline: 1.0176x; 1.0176x over previous
#include <cuda_runtime.h>

// Gumbel-Sinkhorn, multiplicative form; TWO matrices per CTA, interleaved.
//   E = exp((gamma + noise) * 5)
//   repeat niters: r_i = 1/sum_j E_ij c_j ;  c_j = 1/sum_i E_ij r_i
//   out_ij = E_ij * r_i * c_j
//
// CTA = 256 threads, matrices A = 2*bid, B = 2*bid+1.
// Thread t = (row r = t>>1, half h = t&1) caches E[r][64h..64h+63] of BOTH
// matrices in registers (64+64 floats). Row passes are pure register FFMA
// (c read as conflict-free dual-broadcast LDS.128 via a +68 half offset).
// Col pass: warp w sweeps rows 16w..16w+15 (which its own lanes computed r
// for) with full-width LDS.128 row reads; cross-warp column reduce via part
// buffers. A and B are interleaved instruction-by-instruction so one
// matrix's latency chain hides the other's; barriers are shared (1 barrier
// per matrix-iteration instead of 2).

#define NN 128
#define STRIDE 132     // E row stride (floats): col-direction reads conflict-free
#define CS 136         // c vector storage: half h at offset 68*h (bank-staggered)
#define NT 256

__device__ __forceinline__ float frcp(float x) { return __fdividef(1.0f, x); }

__global__ __launch_bounds__(NT, 1) void sinkhorn_pair(
    const float* __restrict__ gamma,
    const float* __restrict__ noise,
    const int*   __restrict__ niters_p,
    float*       __restrict__ out,
    int B)
{
    extern __shared__ float smem[];
    float* EsA  = smem;                      // NN*STRIDE
    float* EsB  = EsA + NN * STRIDE;         // NN*STRIDE
    float* c_sA = EsB + NN * STRIDE;         // CS
    float* c_sB = c_sA + CS;                 // CS
    float* r_sA = c_sB + CS;                 // NN (epilogue only)
    float* r_sB = r_sA + NN;                 // NN
    float* partA = r_sB + NN;                // 8*NN
    float* partB = partA + 8 * NN;           // 8*NN

    const int tid = threadIdx.x;
    const int w   = tid >> 5;                // warp 0..7
    const int l   = tid & 31;                // lane
    const int row = tid >> 1;                // 0..127
    const int h   = tid & 1;                 // half
    const int niters = *niters_p;

    const long long mA = 2LL * blockIdx.x;
    const long long mB = mA + 1;
    const bool hasB = (mB < B);

    // ---- Prologue: E = exp((gamma + noise)*5) for both matrices ----
    const float4* g4  = reinterpret_cast<const float4*>(gamma);
    const float4* nA4 = reinterpret_cast<const float4*>(noise + mA * (NN * NN));
    const float4* nB4 = reinterpret_cast<const float4*>(noise + mB * (NN * NN));
    #pragma unroll
    for (int k = 0; k < 16; ++k) {
        int v  = k * NT + tid;               // float4 index 0..4095
        int i  = v >> 5;
        int j4 = (v & 31) * 4;
        float4 g = g4[v];
        float4 a = nA4[v];
        float4 e;
        e.x = __expf((g.x + a.x) * 5.f);
        e.y = __expf((g.y + a.y) * 5.f);
        e.z = __expf((g.z + a.z) * 5.f);
        e.w = __expf((g.w + a.w) * 5.f);
        *reinterpret_cast<float4*>(&EsA[i * STRIDE + j4]) = e;
        if (hasB) {
            float4 b = nB4[v];
            float4 f;
            f.x = __expf((g.x + b.x) * 5.f);
            f.y = __expf((g.y + b.y) * 5.f);
            f.z = __expf((g.z + b.z) * 5.f);
            f.w = __expf((g.w + b.w) * 5.f);
            *reinterpret_cast<float4*>(&EsB[i * STRIDE + j4]) = f;
        }
    }
    if (tid < CS) { c_sA[tid] = 1.0f; c_sB[tid] = 1.0f; }
    __syncthreads();

    // ---- Register half-row caches for both matrices ----
    float rowA[64], rowB[64];
    {
        const float* pa = &EsA[row * STRIDE + 64 * h];
        const float* pb = &EsB[row * STRIDE + 64 * h];
        #pragma unroll
        for (int m = 0; m < 16; ++m) {
            float4 ea = *reinterpret_cast<const float4*>(&pa[4 * m]);
            rowA[4 * m + 0] = ea.x; rowA[4 * m + 1] = ea.y;
            rowA[4 * m + 2] = ea.z; rowA[4 * m + 3] = ea.w;
            float4 eb = *reinterpret_cast<const float4*>(&pb[4 * m]);
            rowB[4 * m + 0] = eb.x; rowB[4 * m + 1] = eb.y;
            rowB[4 * m + 2] = eb.z; rowB[4 * m + 3] = eb.w;
        }
    }

    const float* cbA = c_sA + 68 * h;        // this thread's half of c (staggered)
    const float* cbB = c_sB + 68 * h;

    float rA = 1.0f, rB = 1.0f;

    // ---- Sinkhorn iterations ----
    for (int it = 0; it < niters; ++it) {
        // Row passes (A and B interleaved), pure register FFMA.
        float a0 = 0.f, a1 = 0.f, a2 = 0.f, a3 = 0.f;
        float b0 = 0.f, b1 = 0.f, b2 = 0.f, b3 = 0.f;
        #pragma unroll
        for (int m = 0; m < 16; ++m) {
            float4 ca = *reinterpret_cast<const float4*>(&cbA[4 * m]);
            a0 += rowA[4 * m + 0] * ca.x;
            a1 += rowA[4 * m + 1] * ca.y;
            a2 += rowA[4 * m + 2] * ca.z;
            a3 += rowA[4 * m + 3] * ca.w;
            float4 cb = *reinterpret_cast<const float4*>(&cbB[4 * m]);
            b0 += rowB[4 * m + 0] * cb.x;
            b1 += rowB[4 * m + 1] * cb.y;
            b2 += rowB[4 * m + 2] * cb.z;
            b3 += rowB[4 * m + 3] * cb.w;
        }
        float SA = (a0 + a1) + (a2 + a3);
        float SB = (b0 + b1) + (b2 + b3);
        SA += __shfl_xor_sync(0xffffffffu, SA, 1);   // combine halves
        SB += __shfl_xor_sync(0xffffffffu, SB, 1);
        rA = frcp(SA);
        rB = frcp(SB);

        // Col passes: warp w sweeps rows 16w..16w+15 of both matrices.
        // Row 16w+k's r lives in lanes 2k/2k+1 of this same warp.
        float pa0 = 0.f, pa1 = 0.f, pa2 = 0.f, pa3 = 0.f;
        float pb0 = 0.f, pb1 = 0.f, pb2 = 0.f, pb3 = 0.f;
        #pragma unroll
        for (int k = 0; k < 16; ++k) {
            int i = 16 * w + k;
            float ria = __shfl_sync(0xffffffffu, rA, 2 * k);
            float4 ea = *reinterpret_cast<const float4*>(&EsA[i * STRIDE + 4 * l]);
            pa0 += ea.x * ria;
            pa1 += ea.y * ria;
            pa2 += ea.z * ria;
            pa3 += ea.w * ria;
            float rib = __shfl_sync(0xffffffffu, rB, 2 * k);
            float4 eb = *reinterpret_cast<const float4*>(&EsB[i * STRIDE + 4 * l]);
            pb0 += eb.x * rib;
            pb1 += eb.y * rib;
            pb2 += eb.z * rib;
            pb3 += eb.w * rib;
        }
        float4 qa; qa.x = pa0; qa.y = pa1; qa.z = pa2; qa.w = pa3;
        *reinterpret_cast<float4*>(&partA[w * NN + 4 * l]) = qa;
        float4 qb; qb.x = pb0; qb.y = pb1; qb.z = pb2; qb.w = pb3;
        *reinterpret_cast<float4*>(&partB[w * NN + 4 * l]) = qb;
        __syncthreads();

        // Cross-warp column reduce: threads 0..127 -> A, 128..255 -> B.
        if (tid < NN) {
            int j = tid;
            float T = 0.f;
            #pragma unroll
            for (int q = 0; q < 8; ++q) T += partA[q * NN + j];
            c_sA[j + ((j >> 6) << 2)] = frcp(T);
        } else {
            int j = tid - NN;
            float T = 0.f;
            #pragma unroll
            for (int q = 0; q < 8; ++q) T += partB[q * NN + j];
            c_sB[j + ((j >> 6) << 2)] = frcp(T);
        }
        __syncthreads();
    }

    // ---- Stash r for the epilogue (lane h==0 of each row pair) ----
    if (!h) { r_sA[row] = rA; r_sB[row] = rB; }
    __syncthreads();

    // ---- Epilogue: out = E * r * c ----
    float4* oA4 = reinterpret_cast<float4*>(out + mA * (NN * NN));
    float4* oB4 = reinterpret_cast<float4*>(out + mB * (NN * NN));
    #pragma unroll
    for (int k = 0; k < 16; ++k) {
        int v  = k * NT + tid;
        int i  = v >> 5;
        int j4 = (v & 31) * 4;
        int js = j4 + ((j4 >> 6) << 2);      // slotted c index
        {
            float ri = r_sA[i];
            float4 c = *reinterpret_cast<const float4*>(&c_sA[js]);
            float4 e = *reinterpret_cast<const float4*>(&EsA[i * STRIDE + j4]);
            float4 o;
            o.x = e.x * ri * c.x;
            o.y = e.y * ri * c.y;
            o.z = e.z * ri * c.z;
            o.w = e.w * ri * c.w;
            oA4[v] = o;
        }
        if (hasB) {
            float ri = r_sB[i];
            float4 c = *reinterpret_cast<const float4*>(&c_sB[js]);
            float4 e = *reinterpret_cast<const float4*>(&EsB[i * STRIDE + j4]);
            float4 o;
            o.x = e.x * ri * c.x;
            o.y = e.y * ri * c.y;
            o.z = e.z * ri * c.z;
            o.w = e.w * ri * c.w;
            oB4[v] = o;
        }
    }
}

extern "C" void kernel_launch(void* const* d_in, const int* in_sizes, int n_in,
                              void* d_out, int out_size)
{
    // Identify inputs by element count:
    //   gamma: 128*128, noise: B*128*128 (largest), niters: 1
    int gi = -1, ni = -1, si = -1;
    long long best = -1;
    for (int k = 0; k < n_in; ++k) {
        if (in_sizes[k] == 1) { si = k; }
        else if (in_sizes[k] == NN * NN && gi < 0) { gi = k; }
        if ((long long)in_sizes[k] > best) { best = in_sizes[k]; ni = k; }
    }
    if (ni == gi) {
        for (int k = 0; k < n_in; ++k)
            if (k != gi && in_sizes[k] == NN * NN) { ni = k; break; }
    }

    const float* gamma = (const float*)d_in[gi];
    const float* noise = (const float*)d_in[ni];
    const int*   nit   = (const int*)d_in[si];
    float* out = (float*)d_out;

    int B = in_sizes[ni] / (NN * NN);

    const int smem_bytes =
        (2 * NN * STRIDE + 2 * CS + 2 * NN + 16 * NN) * (int)sizeof(float);
    static bool attr_set = false;
    if (!attr_set) {
        cudaFuncSetAttribute(sinkhorn_pair,
                             cudaFuncAttributeMaxDynamicSharedMemorySize,
                             smem_bytes);
        attr_set = true;
    }

    int grid = (B + 1) / 2;
    sinkhorn_pair<<<grid, NT, smem_bytes>>>(gamma, noise, nit, out, B);
}

// round 8
// speedup vs baseline: 1.4950x; 1.4691x over previous
#include <cuda_runtime.h>

// Gumbel-Sinkhorn, multiplicative form (R3 chassis, shuffle-free col pass).
//   E = exp((gamma + noise) * 5)            (once)
//   repeat niters: r_i = 1/sum_j E_ij c_j ;  c_j = 1/sum_i E_ij r_i
//   out_ij = E_ij * r_i * c_j
//
// One CTA (128 threads) per matrix, 2 CTAs/SM.
//  - Row pass: thread t holds row t of E in 128 registers; c read as float4
//    broadcast LDS.
//  - Col pass: warp w sweeps rows 32w..32w+31 with conflict-free LDS.128 row
//    loads. r for those rows was computed by THIS warp's own lanes: it goes
//    through shared memory with only a __syncwarp() (no CTA barrier), read
//    back as 8 broadcast LDS.128 — independent, pipelinable loads instead of
//    32 serial shuffle->FMA dependency chains (the R3 stall source).
//  - Cross-warp column reduce via a small part buffer (the only 2 CTA
//    barriers per iteration).

#define NN 128
#define STRIDE 132           // float4-aligned rows; column accesses conflict-free
#define TEMP_INV 5.0f

__global__ __launch_bounds__(128) void sinkhorn_kernel(
    const float* __restrict__ gamma,
    const float* __restrict__ noise,
    const int*   __restrict__ niters_p,
    float*       __restrict__ out)
{
    extern __shared__ float smem[];
    float* Es   = smem;                    // NN * STRIDE
    float* r_s  = smem + NN * STRIDE;      // NN
    float* c_s  = r_s + NN;                // NN
    float* part = c_s + NN;                // 4 * NN  cross-warp column partials

    const int tid = threadIdx.x;
    const int w   = tid >> 5;
    const int l   = tid & 31;
    const long long base = (long long)blockIdx.x * (NN * NN);
    const int niters = *niters_p;

    // ---- Prologue: E = exp((gamma + noise) * 5), coalesced float4 ----
    const float4* g4 = reinterpret_cast<const float4*>(gamma);
    const float4* n4 = reinterpret_cast<const float4*>(noise + base);
    #pragma unroll
    for (int k = 0; k < 32; ++k) {
        int v  = k * 128 + tid;           // float4 index 0..4095
        int i  = v >> 5;                  // row
        int j4 = (v & 31) * 4;            // col
        float4 g = g4[v];
        float4 u = n4[v];
        float4 e;
        e.x = __expf((g.x + u.x) * TEMP_INV);
        e.y = __expf((g.y + u.y) * TEMP_INV);
        e.z = __expf((g.z + u.z) * TEMP_INV);
        e.w = __expf((g.w + u.w) * TEMP_INV);
        *reinterpret_cast<float4*>(&Es[i * STRIDE + j4]) = e;
    }
    c_s[tid] = 1.0f;
    __syncthreads();

    // ---- Register row cache: thread t owns row t ----
    float rowE[NN];
    #pragma unroll
    for (int m = 0; m < 32; ++m) {
        float4 e = *reinterpret_cast<const float4*>(&Es[tid * STRIDE + 4 * m]);
        rowE[4 * m + 0] = e.x;
        rowE[4 * m + 1] = e.y;
        rowE[4 * m + 2] = e.z;
        rowE[4 * m + 3] = e.w;
    }

    // ---- Sinkhorn iterations ----
    for (int it = 0; it < niters; ++it) {
        // Row pass (registers x float4-broadcast c): S_t = sum_j rowE[j]*c[j]
        float a0 = 0.f, a1 = 0.f, a2 = 0.f, a3 = 0.f;
        #pragma unroll
        for (int m = 0; m < 32; ++m) {
            float4 c = *reinterpret_cast<const float4*>(&c_s[4 * m]);
            a0 += rowE[4 * m + 0] * c.x;
            a1 += rowE[4 * m + 1] * c.y;
            a2 += rowE[4 * m + 2] * c.z;
            a3 += rowE[4 * m + 3] * c.w;
        }
        r_s[tid] = __fdividef(1.0f, (a0 + a1) + (a2 + a3));
        __syncwarp();   // warp w's col sweep only needs r_s[32w..32w+31],
                        // written by this same warp — no CTA barrier.

        // Col pass: warp w sweeps rows 32w..32w+31, LDS.128 row loads;
        // r read as 8 independent broadcast LDS.128 (pipelinable).
        float b0 = 0.f, b1 = 0.f, b2 = 0.f, b3 = 0.f;
        #pragma unroll
        for (int g = 0; g < 8; ++g) {
            float4 rv = *reinterpret_cast<const float4*>(&r_s[32 * w + 4 * g]);
            int i0 = 32 * w + 4 * g;
            float4 e0 = *reinterpret_cast<const float4*>(&Es[(i0 + 0) * STRIDE + 4 * l]);
            b0 += e0.x * rv.x; b1 += e0.y * rv.x; b2 += e0.z * rv.x; b3 += e0.w * rv.x;
            float4 e1 = *reinterpret_cast<const float4*>(&Es[(i0 + 1) * STRIDE + 4 * l]);
            b0 += e1.x * rv.y; b1 += e1.y * rv.y; b2 += e1.z * rv.y; b3 += e1.w * rv.y;
            float4 e2 = *reinterpret_cast<const float4*>(&Es[(i0 + 2) * STRIDE + 4 * l]);
            b0 += e2.x * rv.z; b1 += e2.y * rv.z; b2 += e2.z * rv.z; b3 += e2.w * rv.z;
            float4 e3 = *reinterpret_cast<const float4*>(&Es[(i0 + 3) * STRIDE + 4 * l]);
            b0 += e3.x * rv.w; b1 += e3.y * rv.w; b2 += e3.z * rv.w; b3 += e3.w * rv.w;
        }
        float4 p; p.x = b0; p.y = b1; p.z = b2; p.w = b3;
        *reinterpret_cast<float4*>(&part[w * NN + 4 * l]) = p;
        __syncthreads();

        // Cross-warp column reduce: thread t handles column t (conflict-free)
        float T = (part[0 * NN + tid] + part[1 * NN + tid])
                + (part[2 * NN + tid] + part[3 * NN + tid]);
        c_s[tid] = __fdividef(1.0f, T);
        __syncthreads();
    }

    // ---- Epilogue: out = E * r * c, coalesced float4 ----
    float4* o4 = reinterpret_cast<float4*>(out + base);
    #pragma unroll
    for (int k = 0; k < 32; ++k) {
        int v  = k * 128 + tid;
        int i  = v >> 5;
        int j4 = (v & 31) * 4;
        float ri = r_s[i];
        float4 e = *reinterpret_cast<const float4*>(&Es[i * STRIDE + j4]);
        float4 o;
        o.x = e.x * ri * c_s[j4 + 0];
        o.y = e.y * ri * c_s[j4 + 1];
        o.z = e.z * ri * c_s[j4 + 2];
        o.w = e.w * ri * c_s[j4 + 3];
        o4[v] = o;
    }
}

extern "C" void kernel_launch(void* const* d_in, const int* in_sizes, int n_in,
                              void* d_out, int out_size)
{
    // Identify inputs by element count:
    //   gamma: 128*128, noise: B*128*128 (largest), niters: 1
    int gi = -1, ni = -1, si = -1;
    long long best = -1;
    for (int k = 0; k < n_in; ++k) {
        if (in_sizes[k] == 1) { si = k; }
        else if (in_sizes[k] == NN * NN && gi < 0) { gi = k; }
        if ((long long)in_sizes[k] > best) { best = in_sizes[k]; ni = k; }
    }
    if (ni == gi) {
        for (int k = 0; k < n_in; ++k)
            if (k != gi && in_sizes[k] == NN * NN) { ni = k; break; }
    }

    const float* gamma = (const float*)d_in[gi];
    const float* noise = (const float*)d_in[ni];
    const int*   nit   = (const int*)d_in[si];
    float* out = (float*)d_out;

    int B = in_sizes[ni] / (NN * NN);

    const int smem_bytes = (NN * STRIDE + 2 * NN + 4 * NN) * (int)sizeof(float);
    static bool attr_set = false;
    if (!attr_set) {
        cudaFuncSetAttribute(sinkhorn_kernel,
                             cudaFuncAttributeMaxDynamicSharedMemorySize,
                             smem_bytes);
        attr_set = true;
    }

    sinkhorn_kernel<<<B, 128, smem_bytes>>>(gamma, noise, nit, out);
}